// round 9
// baseline (speedup 1.0000x reference)
#include <cuda_runtime.h>
#include <math.h>

#define BB 4096
#define LL 32
#define HH 6
#define DDIM 300
#define HDD 50
#define NKC 38
#define XSS 308      // Xs / ctx2 stride (floats): conflict-free A-frag LDS
#define KVS 300      // K,V stride
#define MT 64        // rows per CTA = 2 batch rows
#define GT 256       // 8 warps, all across N; warp tile 64 x 40

// Fragment-packed weights: g_Wb[m][((kc*8 + wn)*5 + nc)*32 + lane] =
//   { W[wn*40+nc*8+gid][kc*8+ctg], W[...][kc*8+ctg+4] }  (zero-padded, tf32-rounded)
#define WB_PER_M (NKC * 8 * 5 * 32)
__device__ float2 g_Wb[5][WB_PER_M];

// smem float offsets
#define OFF_K   (MT * XSS)
#define OFF_V   (OFF_K + MT * KVS)
#define OFF_CT  OFF_K                       // ctx2 reuses K/V region, stride XSS
#define OFF_SP  (OFF_CT + MT * XSS)
#define OFF_SA  (OFF_SP + 8 * MT)
#define OFF_SAL (OFF_SA + MT)
#define SMEM_FLOATS (OFF_V + MT * KVS)      // 58112 floats -> 232448 bytes

__device__ __forceinline__ float tf32r(float x) {
    unsigned r;
    asm("cvt.rna.tf32.f32 %0, %1;" : "=r"(r) : "f"(x));
    return __uint_as_float(r);
}

__device__ __forceinline__ float tanh_fast(float x) {
    float y;
    asm("tanh.approx.f32 %0, %1;" : "=f"(y) : "f"(x));
    return y;
}

__device__ __forceinline__ void mma8(float c[4], const float a[4], float b0, float b1) {
    asm volatile(
        "mma.sync.aligned.m16n8k8.row.col.f32.tf32.tf32.f32 "
        "{%0,%1,%2,%3},{%4,%5,%6,%7},{%8,%9},{%0,%1,%2,%3};"
        : "+f"(c[0]), "+f"(c[1]), "+f"(c[2]), "+f"(c[3])
        : "r"(__float_as_uint(a[0])), "r"(__float_as_uint(a[1])),
          "r"(__float_as_uint(a[2])), "r"(__float_as_uint(a[3])),
          "r"(__float_as_uint(b0)), "r"(__float_as_uint(b1)));
}

__global__ void prep_kernel(const float* __restrict__ Wq, const float* __restrict__ Wk,
                            const float* __restrict__ Wv, const float* __restrict__ Wo,
                            const float* __restrict__ Va) {
    const float* src;
    int m = blockIdx.y;
    switch (m) {
        case 0: src = Wq; break;
        case 1: src = Wk; break;
        case 2: src = Wv; break;
        case 3: src = Wo; break;
        default: src = Va; break;
    }
    float2* dst = g_Wb[m];
    for (int idx = blockIdx.x * blockDim.x + threadIdx.x; idx < WB_PER_M;
         idx += gridDim.x * blockDim.x) {
        int lane = idx & 31;
        int t1   = idx >> 5;
        int nc   = t1 % 5;
        int t2   = t1 / 5;
        int wn   = t2 & 7;
        int kc   = t2 >> 3;
        int gid = lane >> 2, ctg = lane & 3;
        int n = wn * 40 + nc * 8 + gid;
        int k = kc * 8 + ctg;
        float2 f = make_float2(0.f, 0.f);
        if (n < DDIM) {
            if (k < DDIM)     f.x = tf32r(src[n * DDIM + k]);
            if (k + 4 < DDIM) f.y = tf32r(src[n * DDIM + k + 4]);
        }
        dst[idx] = f;
    }
}

// one k-chunk: prefetch kc+3 into this buffer after consuming it
__device__ __forceinline__ void gstep(const float* __restrict__ S,
                                      const float2* __restrict__ wb0,
                                      int kc, int gid, int ctg,
                                      float2 b[5], float c[4][5][4]) {
    // issue prefetch for kc+3 early (fresh regs; WAR vs mma reads renamed by ptxas)
    float2 nb[5];
    const bool ld = (kc + 3 < NKC);
    const float2* w2 = wb0 + (size_t)(kc + 3) * (8 * 5 * 32);
    #pragma unroll
    for (int nc = 0; nc < 5; ++nc)
        nb[nc] = ld ? w2[nc * 32] : make_float2(0.f, 0.f);

    const int k0 = kc * 8;
    float a[4][4];
    #pragma unroll
    for (int mf = 0; mf < 4; ++mf) {
        const float* xr = S + (mf * 16 + gid) * XSS + k0;
        a[mf][0] = xr[ctg];
        a[mf][1] = xr[8 * XSS + ctg];
        a[mf][2] = xr[ctg + 4];
        a[mf][3] = xr[8 * XSS + ctg + 4];
    }
    #pragma unroll
    for (int nc = 0; nc < 5; ++nc)
        #pragma unroll
        for (int mf = 0; mf < 4; ++mf)
            mma8(c[mf][nc], a[mf], b[nc].x, b[nc].y);

    #pragma unroll
    for (int nc = 0; nc < 5; ++nc) b[nc] = nb[nc];
}

// GEMM mainloop: A = S[64][XSS] (smem), B = packed fragments, depth-3 prefetch
__device__ __forceinline__ void gemm_main(const float* __restrict__ S,
                                          const float2* __restrict__ wb0,
                                          int gid, int ctg, float c[4][5][4]) {
    #pragma unroll
    for (int mf = 0; mf < 4; ++mf)
        #pragma unroll
        for (int nc = 0; nc < 5; ++nc)
            #pragma unroll
            for (int i = 0; i < 4; ++i) c[mf][nc][i] = 0.f;

    float2 b0[5], b1[5], b2[5];
    #pragma unroll
    for (int nc = 0; nc < 5; ++nc) {
        b0[nc] = wb0[nc * 32];
        b1[nc] = wb0[(size_t)(8 * 5 * 32) + nc * 32];
        b2[nc] = wb0[(size_t)2 * (8 * 5 * 32) + nc * 32];
    }

    #pragma unroll 1
    for (int kb = 0; kb < NKC / 3; ++kb) {        // 12 groups = kc 0..35
        int kc = kb * 3;
        gstep(S, wb0, kc + 0, gid, ctg, b0, c);
        gstep(S, wb0, kc + 1, gid, ctg, b1, c);
        gstep(S, wb0, kc + 2, gid, ctg, b2, c);
    }
    gstep(S, wb0, 36, gid, ctg, b0, c);
    gstep(S, wb0, 37, gid, ctg, b1, c);
}

__global__ __launch_bounds__(GT, 1)
void fused_kernel(const int* __restrict__ title,
                  const float* __restrict__ emb,
                  const float* __restrict__ pos,
                  const float* __restrict__ bq,
                  const float* __restrict__ bk,
                  const float* __restrict__ bv,
                  const float* __restrict__ bo,
                  const float* __restrict__ ba,
                  const float* __restrict__ qw,
                  float* __restrict__ out) {
    extern __shared__ float sm[];
    float* Xs = sm;                 // [64][308]  x -> Q -> ctx
    float* SK = sm + OFF_K;         // [64][300]
    float* SV = sm + OFF_V;         // [64][300]
    float* CT = sm + OFF_CT;        // [64][308]  ctx2 (reuses K/V region)
    float* SP = sm + OFF_SP;
    float* SA = sm + OFF_SA;
    float* SAL = sm + OFF_SAL;

    const int tid = threadIdx.x;
    const int lane = tid & 31, wid = tid >> 5;
    const int gid = lane >> 2, ctg = lane & 3;
    const int wn = wid;
    const int r0 = blockIdx.x * MT;

    // tokens live in Xs pad cols [304..307] (no static smem)
    if (tid < MT) ((int*)Xs)[tid * XSS + 304] = title[r0 + tid];
    __syncthreads();

    // ---- gather x = tf32(emb[tok] + pos); cols 300..303 zeroed ----
    for (int idx = tid; idx < MT * 76; idx += GT) {
        int r = idx / 76, j = idx - r * 76;
        float4 v = make_float4(0.f, 0.f, 0.f, 0.f);
        if (j < 75) {
            int tok = ((const int*)Xs)[r * XSS + 304];
            float4 e = *(const float4*)&emb[(size_t)tok * DDIM + 4 * j];
            float4 p = *(const float4*)&pos[(r & (LL - 1)) * DDIM + 4 * j];
            v.x = tf32r(e.x + p.x); v.y = tf32r(e.y + p.y);
            v.z = tf32r(e.z + p.z); v.w = tf32r(e.w + p.w);
        }
        *(float4*)&Xs[r * XSS + 4 * j] = v;
    }
    __syncthreads();

    float c[4][5][4];

    // ---- K = x @ Wk^T + bk -> SK ----
    gemm_main(Xs, g_Wb[1] + (size_t)wn * 5 * 32 + lane, gid, ctg, c);
    #pragma unroll
    for (int mf = 0; mf < 4; ++mf)
        #pragma unroll
        for (int nc = 0; nc < 5; ++nc) {
            int n = wn * 40 + nc * 8 + 2 * ctg;
            if (n < DDIM) {
                float b0 = bk[n], b1 = bk[n + 1];
                #pragma unroll
                for (int h = 0; h < 2; ++h) {
                    int r = mf * 16 + gid + h * 8;
                    SK[r * KVS + n]     = c[mf][nc][2 * h]     + b0;
                    SK[r * KVS + n + 1] = c[mf][nc][2 * h + 1] + b1;
                }
            }
        }

    // ---- V = x @ Wv^T + bv -> SV ----
    gemm_main(Xs, g_Wb[2] + (size_t)wn * 5 * 32 + lane, gid, ctg, c);
    #pragma unroll
    for (int mf = 0; mf < 4; ++mf)
        #pragma unroll
        for (int nc = 0; nc < 5; ++nc) {
            int n = wn * 40 + nc * 8 + 2 * ctg;
            if (n < DDIM) {
                float b0 = bv[n], b1 = bv[n + 1];
                #pragma unroll
                for (int h = 0; h < 2; ++h) {
                    int r = mf * 16 + gid + h * 8;
                    SV[r * KVS + n]     = c[mf][nc][2 * h]     + b0;
                    SV[r * KVS + n + 1] = c[mf][nc][2 * h + 1] + b1;
                }
            }
        }

    // ---- Q = (x @ Wq^T + bq)/sqrt(HD) -> Xs (after all warps done reading x) ----
    gemm_main(Xs, g_Wb[0] + (size_t)wn * 5 * 32 + lane, gid, ctg, c);
    const float rs = rsqrtf((float)HDD);
    __syncthreads();
    #pragma unroll
    for (int mf = 0; mf < 4; ++mf)
        #pragma unroll
        for (int nc = 0; nc < 5; ++nc) {
            int n = wn * 40 + nc * 8 + 2 * ctg;
            if (n < DDIM) {
                float b0 = bq[n], b1 = bq[n + 1];
                #pragma unroll
                for (int h = 0; h < 2; ++h) {
                    int r = mf * 16 + gid + h * 8;
                    Xs[r * XSS + n]     = (c[mf][nc][2 * h]     + b0) * rs;
                    Xs[r * XSS + n + 1] = (c[mf][nc][2 * h + 1] + b1) * rs;
                }
            }
        }
    __syncthreads();

    // ---- attention: 12 (brow,head) pairs over 8 warps; ctx -> Xs (tf32r) ----
    for (int p = wid; p < 2 * HH; p += 8) {
        int br = p / HH, h = p - HH * (p / HH);
        int off = h * HDD;
        const float* Qb = Xs + (br * LL) * XSS;
        const float* Kb = SK + (br * LL) * KVS;
        const float* Vb = SV + (br * LL) * KVS;
        const int i = lane;
        float s[LL];
        #pragma unroll
        for (int j = 0; j < LL; ++j) s[j] = 0.f;
        for (int hd2 = 0; hd2 < HDD / 2; ++hd2) {
            float2 q2 = *(const float2*)&Qb[i * XSS + off + 2 * hd2];
            #pragma unroll
            for (int j = 0; j < LL; ++j) {
                float2 k2 = *(const float2*)&Kb[j * KVS + off + 2 * hd2];
                s[j] = fmaf(q2.x, k2.x, fmaf(q2.y, k2.y, s[j]));
            }
        }
        float m = -1e30f;
        #pragma unroll
        for (int j = 0; j < LL; ++j) m = fmaxf(m, s[j]);
        float sum = 0.f;
        #pragma unroll
        for (int j = 0; j < LL; ++j) { s[j] = __expf(s[j] - m); sum += s[j]; }
        float inv = 1.f / sum;
        #pragma unroll
        for (int j = 0; j < LL; ++j) s[j] *= inv;
        for (int hd2 = 0; hd2 < HDD / 2; ++hd2) {
            float cx = 0.f, cy = 0.f;
            #pragma unroll
            for (int j = 0; j < LL; ++j) {
                float2 v2 = *(const float2*)&Vb[j * KVS + off + 2 * hd2];
                cx = fmaf(s[j], v2.x, cx);
                cy = fmaf(s[j], v2.y, cy);
            }
            float2 o2 = make_float2(tf32r(cx), tf32r(cy));
            *(float2*)&Xs[(br * LL + i) * XSS + off + 2 * hd2] = o2;
        }
    }
    __syncthreads();

    // ---- ctx2 = ctx @ Wo^T + bo -> CT (reuses K/V region; pads zeroed) ----
    gemm_main(Xs, g_Wb[3] + (size_t)wn * 5 * 32 + lane, gid, ctg, c);
    #pragma unroll
    for (int mf = 0; mf < 4; ++mf)
        #pragma unroll
        for (int nc = 0; nc < 5; ++nc) {
            int n = wn * 40 + nc * 8 + 2 * ctg;
            if (n < DDIM) {
                float b0 = bo[n], b1 = bo[n + 1];
                #pragma unroll
                for (int h = 0; h < 2; ++h) {
                    int r = mf * 16 + gid + h * 8;
                    CT[r * XSS + n]     = c[mf][nc][2 * h]     + b0;
                    CT[r * XSS + n + 1] = c[mf][nc][2 * h + 1] + b1;
                }
            }
        }
    CT[(tid >> 2) * XSS + 300 + (tid & 3)] = 0.f;   // zero pad cols 300..303
    __syncthreads();

    // ---- scores: a[l] = sum_n tanh(ctx2 @ Va^T + ba)[l][n] * qw[n] ----
    gemm_main(CT, g_Wb[4] + (size_t)wn * 5 * 32 + lane, gid, ctg, c);
    {
        float p[4][2];
        #pragma unroll
        for (int mf = 0; mf < 4; ++mf) { p[mf][0] = 0.f; p[mf][1] = 0.f; }
        #pragma unroll
        for (int mf = 0; mf < 4; ++mf)
            #pragma unroll
            for (int nc = 0; nc < 5; ++nc)
                #pragma unroll
                for (int i = 0; i < 4; ++i) {
                    int n = wn * 40 + nc * 8 + 2 * ctg + (i & 1);
                    if (n < DDIM) {
                        float tv = tanh_fast(c[mf][nc][i] + ba[n]);
                        p[mf][i >> 1] = fmaf(tv, qw[n], p[mf][i >> 1]);
                    }
                }
        #pragma unroll
        for (int mf = 0; mf < 4; ++mf)
            #pragma unroll
            for (int h = 0; h < 2; ++h) {
                float v = p[mf][h];
                v += __shfl_xor_sync(0xffffffffu, v, 1);
                v += __shfl_xor_sync(0xffffffffu, v, 2);
                p[mf][h] = v;
            }
        if (ctg == 0) {
            #pragma unroll
            for (int mf = 0; mf < 4; ++mf)
                #pragma unroll
                for (int h = 0; h < 2; ++h) {
                    int r = mf * 16 + gid + h * 8;
                    SP[wn * MT + r] = p[mf][h];
                }
        }
    }
    __syncthreads();
    if (tid < MT) {
        float s = 0.f;
        #pragma unroll
        for (int w = 0; w < 8; ++w) s += SP[w * MT + tid];
        SA[tid] = s;
    }
    __syncthreads();

    if (wid < 2) {      // one warp per batch row
        float v = SA[wid * LL + lane];
        float m = v;
        #pragma unroll
        for (int o = 16; o; o >>= 1) m = fmaxf(m, __shfl_xor_sync(0xffffffffu, m, o));
        float e = __expf(v - m);
        float sum = e;
        #pragma unroll
        for (int o = 16; o; o >>= 1) sum += __shfl_xor_sync(0xffffffffu, sum, o);
        SAL[wid * LL + lane] = e / sum;
    }
    __syncthreads();

    for (int idx = tid; idx < 2 * DDIM; idx += GT) {
        int bb = idx / DDIM, d = idx - bb * DDIM;
        float o = 0.f;
        #pragma unroll
        for (int l = 0; l < LL; ++l)
            o = fmaf(SAL[bb * LL + l], CT[(bb * LL + l) * XSS + d], o);
        out[(size_t)(blockIdx.x * 2 + bb) * DDIM + d] = o;
    }
}

extern "C" void kernel_launch(void* const* d_in, const int* in_sizes, int n_in,
                              void* d_out, int out_size) {
    const int*   title = (const int*)  d_in[0];
    const float* emb   = (const float*)d_in[1];
    const float* pos   = (const float*)d_in[2];
    const float* Wq    = (const float*)d_in[3];
    const float* bq    = (const float*)d_in[4];
    const float* Wk    = (const float*)d_in[5];
    const float* bk    = (const float*)d_in[6];
    const float* Wv    = (const float*)d_in[7];
    const float* bv    = (const float*)d_in[8];
    const float* Wo    = (const float*)d_in[9];
    const float* bo    = (const float*)d_in[10];
    const float* Va    = (const float*)d_in[11];
    const float* ba    = (const float*)d_in[12];
    const float* qw    = (const float*)d_in[13];
    float* out = (float*)d_out;

    size_t shbytes = (size_t)SMEM_FLOATS * sizeof(float);   // 232448 bytes
    cudaFuncSetAttribute(fused_kernel,
                         cudaFuncAttributeMaxDynamicSharedMemorySize, (int)shbytes);

    dim3 pgrid(48, 5);
    prep_kernel<<<pgrid, 256>>>(Wq, Wk, Wv, Wo, Va);

    fused_kernel<<<BB * LL / MT, GT, shbytes>>>(title, emb, pos,
                                                bq, bk, bv, bo, ba, qw, out);
}

// round 10
// speedup vs baseline: 1.4541x; 1.4541x over previous
#include <cuda_runtime.h>
#include <cuda_fp16.h>
#include <math.h>

#define BB 4096
#define LL 32
#define HH 6
#define DDIM 300
#define HDD 50
#define NKC16 19       // k-chunks of 16 (K padded to 304)
#define HS 328         // half-stride of Xs/K/V rows (half2 stride 164 ≡ 4 mod 32 -> conflict-free)
#define MT 64          // rows per CTA = 2 batch rows
#define GT 256         // 8 warps, all across N; warp tile 64 x 40

// Fragment-packed fp16 weights: g_Wh[m][((kc*8+wn)*5+nc)*32 + lane] = uint2{
//   half2(W[n][k], W[n][k+1]), half2(W[n][k+8], W[n][k+9]) }, n=wn*40+nc*8+gid, k=kc*16+2*tig
#define WB16 (NKC16 * 8 * 5 * 32)
__device__ uint2 g_Wh[5][WB16];

// smem byte offsets
#define X_OFF   0           // half [64][328] : x -> Q -> ctx -> ctx2(fp16 copy)
#define K_OFF   41984       // half [64][328]
#define V_OFF   83968       // half [64][328]
#define CT_OFF  41984       // float [64][300] ctx2 fp32 (overlays K/V region after attention)
#define SP_OFF  125952      // float [8][64]
#define SA_OFF  128000      // float [64]
#define SAL_OFF 128256      // float [64]
#define SMEM_BYTES 128512

__device__ __forceinline__ float tanh_fast(float x) {
    float y;
    asm("tanh.approx.f32 %0, %1;" : "=f"(y) : "f"(x));
    return y;
}

__device__ __forceinline__ void mma16(float c[4], const unsigned a[4],
                                      unsigned b0, unsigned b1) {
    asm volatile(
        "mma.sync.aligned.m16n8k16.row.col.f32.f16.f16.f32 "
        "{%0,%1,%2,%3},{%4,%5,%6,%7},{%8,%9},{%0,%1,%2,%3};"
        : "+f"(c[0]), "+f"(c[1]), "+f"(c[2]), "+f"(c[3])
        : "r"(a[0]), "r"(a[1]), "r"(a[2]), "r"(a[3]), "r"(b0), "r"(b1));
}

__global__ void prep_kernel(const float* __restrict__ Wq, const float* __restrict__ Wk,
                            const float* __restrict__ Wv, const float* __restrict__ Wo,
                            const float* __restrict__ Va) {
    const float* src;
    int m = blockIdx.y;
    switch (m) {
        case 0: src = Wq; break;
        case 1: src = Wk; break;
        case 2: src = Wv; break;
        case 3: src = Wo; break;
        default: src = Va; break;
    }
    uint2* dst = g_Wh[m];
    for (int idx = blockIdx.x * blockDim.x + threadIdx.x; idx < WB16;
         idx += gridDim.x * blockDim.x) {
        int lane = idx & 31;
        int t1   = idx >> 5;
        int nc   = t1 % 5;
        int t2   = t1 / 5;
        int wn   = t2 & 7;
        int kc   = t2 >> 3;
        int gid = lane >> 2, tig = lane & 3;
        int n = wn * 40 + nc * 8 + gid;
        int k = kc * 16 + 2 * tig;
        float w0 = 0.f, w1 = 0.f, w2 = 0.f, w3 = 0.f;
        if (n < DDIM) {
            if (k < DDIM)     w0 = src[n * DDIM + k];
            if (k + 1 < DDIM) w1 = src[n * DDIM + k + 1];
            if (k + 8 < DDIM) w2 = src[n * DDIM + k + 8];
            if (k + 9 < DDIM) w3 = src[n * DDIM + k + 9];
        }
        uint2 f;
        f.x = (unsigned)__half_as_ushort(__float2half_rn(w0)) |
              ((unsigned)__half_as_ushort(__float2half_rn(w1)) << 16);
        f.y = (unsigned)__half_as_ushort(__float2half_rn(w2)) |
              ((unsigned)__half_as_ushort(__float2half_rn(w3)) << 16);
        dst[idx] = f;
    }
}

// GEMM mainloop: A = S (half, 64 rows x HS), B = packed fp16 fragments, depth-1 prefetch
__device__ __forceinline__ void gemm_main(const __half* __restrict__ S,
                                          const uint2* __restrict__ wb0,
                                          int gid, int tig, float c[4][5][4]) {
    #pragma unroll
    for (int mf = 0; mf < 4; ++mf)
        #pragma unroll
        for (int nc = 0; nc < 5; ++nc)
            #pragma unroll
            for (int i = 0; i < 4; ++i) c[mf][nc][i] = 0.f;

    uint2 bcur[5];
    #pragma unroll
    for (int nc = 0; nc < 5; ++nc) bcur[nc] = wb0[nc * 32];

    #pragma unroll 2
    for (int kc = 0; kc < NKC16; ++kc) {
        uint2 bnxt[5];
        if (kc + 1 < NKC16) {
            const uint2* w2 = wb0 + (size_t)(kc + 1) * (8 * 5 * 32);
            #pragma unroll
            for (int nc = 0; nc < 5; ++nc) bnxt[nc] = w2[nc * 32];
        }
        const int k0 = kc * 16 + 2 * tig;
        unsigned a[4][4];
        #pragma unroll
        for (int mf = 0; mf < 4; ++mf) {
            const __half* xr = S + (mf * 16 + gid) * HS + k0;
            a[mf][0] = *(const unsigned*)&xr[0];
            a[mf][1] = *(const unsigned*)&xr[8 * HS];
            a[mf][2] = *(const unsigned*)&xr[8];
            a[mf][3] = *(const unsigned*)&xr[8 * HS + 8];
        }
        #pragma unroll
        for (int nc = 0; nc < 5; ++nc)
            #pragma unroll
            for (int mf = 0; mf < 4; ++mf)
                mma16(c[mf][nc], a[mf], bcur[nc].x, bcur[nc].y);
        #pragma unroll
        for (int nc = 0; nc < 5; ++nc) bcur[nc] = bnxt[nc];
    }
}

__global__ __launch_bounds__(GT, 1)
void fused_kernel(const int* __restrict__ title,
                  const float* __restrict__ emb,
                  const float* __restrict__ pos,
                  const float* __restrict__ bq,
                  const float* __restrict__ bk,
                  const float* __restrict__ bv,
                  const float* __restrict__ bo,
                  const float* __restrict__ ba,
                  const float* __restrict__ qw,
                  float* __restrict__ out) {
    extern __shared__ char smraw[];
    __half* Xsh = (__half*)(smraw + X_OFF);
    __half* SKh = (__half*)(smraw + K_OFF);
    __half* SVh = (__half*)(smraw + V_OFF);
    float*  CT  = (float*)(smraw + CT_OFF);     // stride 300
    float*  SP  = (float*)(smraw + SP_OFF);
    float*  SA  = (float*)(smraw + SA_OFF);
    float*  SAL = (float*)(smraw + SAL_OFF);
    __shared__ int toks[MT];

    const int tid = threadIdx.x;
    const int lane = tid & 31, wid = tid >> 5;
    const int gid = lane >> 2, tig = lane & 3;
    const int wn = wid;
    const int r0 = blockIdx.x * MT;

    if (tid < MT) toks[tid] = title[r0 + tid];
    __syncthreads();

    // ---- gather x = fp16(emb[tok] + pos); cols 300..327 zero (incl. pads) ----
    for (int idx = tid; idx < MT * 82; idx += GT) {
        int r = idx / 82, j = idx - r * 82;
        uint2 o = make_uint2(0u, 0u);
        if (j < 75) {
            float4 e = *(const float4*)&emb[(size_t)toks[r] * DDIM + 4 * j];
            float4 p = *(const float4*)&pos[(r & (LL - 1)) * DDIM + 4 * j];
            __half2 h0 = __floats2half2_rn(e.x + p.x, e.y + p.y);
            __half2 h1 = __floats2half2_rn(e.z + p.z, e.w + p.w);
            o.x = *(unsigned*)&h0;
            o.y = *(unsigned*)&h1;
        }
        *(uint2*)&Xsh[r * HS + 4 * j] = o;      // j=75..81 zero cols 300..327
    }
    __syncthreads();

    float c[4][5][4];

    // ---- K = x @ Wk^T + bk -> SKh ----
    gemm_main(Xsh, g_Wh[1] + (size_t)wn * 5 * 32 + lane, gid, tig, c);
    #pragma unroll
    for (int mf = 0; mf < 4; ++mf)
        #pragma unroll
        for (int nc = 0; nc < 5; ++nc) {
            int n = wn * 40 + nc * 8 + 2 * tig;
            if (n < DDIM) {
                float b0 = bk[n], b1 = bk[n + 1];
                #pragma unroll
                for (int h = 0; h < 2; ++h) {
                    int r = mf * 16 + gid + h * 8;
                    __half2 hv = __floats2half2_rn(c[mf][nc][2 * h] + b0,
                                                   c[mf][nc][2 * h + 1] + b1);
                    *(__half2*)&SKh[r * HS + n] = hv;
                }
            }
        }

    // ---- V = x @ Wv^T + bv -> SVh ----
    gemm_main(Xsh, g_Wh[2] + (size_t)wn * 5 * 32 + lane, gid, tig, c);
    #pragma unroll
    for (int mf = 0; mf < 4; ++mf)
        #pragma unroll
        for (int nc = 0; nc < 5; ++nc) {
            int n = wn * 40 + nc * 8 + 2 * tig;
            if (n < DDIM) {
                float b0 = bv[n], b1 = bv[n + 1];
                #pragma unroll
                for (int h = 0; h < 2; ++h) {
                    int r = mf * 16 + gid + h * 8;
                    __half2 hv = __floats2half2_rn(c[mf][nc][2 * h] + b0,
                                                   c[mf][nc][2 * h + 1] + b1);
                    *(__half2*)&SVh[r * HS + n] = hv;
                }
            }
        }

    // ---- Q = (x @ Wq^T + bq)/sqrt(HD) -> Xsh (after all warps done with x) ----
    gemm_main(Xsh, g_Wh[0] + (size_t)wn * 5 * 32 + lane, gid, tig, c);
    const float rs = rsqrtf((float)HDD);
    __syncthreads();
    #pragma unroll
    for (int mf = 0; mf < 4; ++mf)
        #pragma unroll
        for (int nc = 0; nc < 5; ++nc) {
            int n = wn * 40 + nc * 8 + 2 * tig;
            if (n < DDIM) {
                float b0 = bq[n], b1 = bq[n + 1];
                #pragma unroll
                for (int h = 0; h < 2; ++h) {
                    int r = mf * 16 + gid + h * 8;
                    __half2 hv = __floats2half2_rn((c[mf][nc][2 * h] + b0) * rs,
                                                   (c[mf][nc][2 * h + 1] + b1) * rs);
                    *(__half2*)&Xsh[r * HS + n] = hv;
                }
            }
        }
    __syncthreads();

    // ---- attention: 12 (brow,head) tasks over 8 warps; ctx -> Xsh (fp16) ----
    for (int p = wid; p < 2 * HH; p += 8) {
        int br = p / HH, h = p - HH * (p / HH);
        int off = h * HDD;
        const __half* Qb = Xsh + (br * LL) * HS;
        const __half* Kb = SKh + (br * LL) * HS;
        const __half* Vb = SVh + (br * LL) * HS;
        const int i = lane;
        float s[LL];
        #pragma unroll
        for (int j = 0; j < LL; ++j) s[j] = 0.f;
        for (int hd2 = 0; hd2 < HDD / 2; ++hd2) {
            float2 q2 = __half22float2(*(const __half2*)&Qb[i * HS + off + 2 * hd2]);
            #pragma unroll
            for (int j = 0; j < LL; ++j) {
                float2 k2 = __half22float2(*(const __half2*)&Kb[j * HS + off + 2 * hd2]);
                s[j] = fmaf(q2.x, k2.x, fmaf(q2.y, k2.y, s[j]));
            }
        }
        float m = -1e30f;
        #pragma unroll
        for (int j = 0; j < LL; ++j) m = fmaxf(m, s[j]);
        float sum = 0.f;
        #pragma unroll
        for (int j = 0; j < LL; ++j) { s[j] = __expf(s[j] - m); sum += s[j]; }
        float inv = 1.f / sum;
        #pragma unroll
        for (int j = 0; j < LL; ++j) s[j] *= inv;
        for (int hd2 = 0; hd2 < HDD / 2; ++hd2) {
            float cx = 0.f, cy = 0.f;
            #pragma unroll
            for (int j = 0; j < LL; ++j) {
                float2 v2 = __half22float2(*(const __half2*)&Vb[j * HS + off + 2 * hd2]);
                cx = fmaf(s[j], v2.x, cx);
                cy = fmaf(s[j], v2.y, cy);
            }
            *(__half2*)&Xsh[(br * LL + i) * HS + off + 2 * hd2] = __floats2half2_rn(cx, cy);
        }
    }
    __syncthreads();

    // ---- ctx2 = ctx @ Wo^T + bo : fp32 -> CT (K/V region), fp16 -> Xsh ----
    gemm_main(Xsh, g_Wh[3] + (size_t)wn * 5 * 32 + lane, gid, tig, c);
    __syncthreads();                              // all warps done reading ctx
    #pragma unroll
    for (int mf = 0; mf < 4; ++mf)
        #pragma unroll
        for (int nc = 0; nc < 5; ++nc) {
            int n = wn * 40 + nc * 8 + 2 * tig;
            if (n < DDIM) {
                float b0 = bo[n], b1 = bo[n + 1];
                #pragma unroll
                for (int h = 0; h < 2; ++h) {
                    int r = mf * 16 + gid + h * 8;
                    float v0 = c[mf][nc][2 * h] + b0;
                    float v1 = c[mf][nc][2 * h + 1] + b1;
                    *(float2*)&CT[r * 300 + n] = make_float2(v0, v1);
                    *(__half2*)&Xsh[r * HS + n] = __floats2half2_rn(v0, v1);
                }
            }
        }
    __syncthreads();

    // ---- scores: a[l] = sum_n tanh(ctx2 @ Va^T + ba)[l][n] * qw[n] ----
    gemm_main(Xsh, g_Wh[4] + (size_t)wn * 5 * 32 + lane, gid, tig, c);
    {
        float p[4][2];
        #pragma unroll
        for (int mf = 0; mf < 4; ++mf) { p[mf][0] = 0.f; p[mf][1] = 0.f; }
        #pragma unroll
        for (int mf = 0; mf < 4; ++mf)
            #pragma unroll
            for (int nc = 0; nc < 5; ++nc)
                #pragma unroll
                for (int i = 0; i < 4; ++i) {
                    int n = wn * 40 + nc * 8 + 2 * tig + (i & 1);
                    if (n < DDIM) {
                        float tv = tanh_fast(c[mf][nc][i] + ba[n]);
                        p[mf][i >> 1] = fmaf(tv, qw[n], p[mf][i >> 1]);
                    }
                }
        #pragma unroll
        for (int mf = 0; mf < 4; ++mf)
            #pragma unroll
            for (int h = 0; h < 2; ++h) {
                float v = p[mf][h];
                v += __shfl_xor_sync(0xffffffffu, v, 1);
                v += __shfl_xor_sync(0xffffffffu, v, 2);
                p[mf][h] = v;
            }
        if (tig == 0) {
            #pragma unroll
            for (int mf = 0; mf < 4; ++mf)
                #pragma unroll
                for (int h = 0; h < 2; ++h) {
                    int r = mf * 16 + gid + h * 8;
                    SP[wn * MT + r] = p[mf][h];
                }
        }
    }
    __syncthreads();
    if (tid < MT) {
        float s = 0.f;
        #pragma unroll
        for (int w = 0; w < 8; ++w) s += SP[w * MT + tid];
        SA[tid] = s;
    }
    __syncthreads();

    if (wid < 2) {      // one warp per batch row
        float v = SA[wid * LL + lane];
        float m = v;
        #pragma unroll
        for (int o = 16; o; o >>= 1) m = fmaxf(m, __shfl_xor_sync(0xffffffffu, m, o));
        float e = __expf(v - m);
        float sum = e;
        #pragma unroll
        for (int o = 16; o; o >>= 1) sum += __shfl_xor_sync(0xffffffffu, sum, o);
        SAL[wid * LL + lane] = e / sum;
    }
    __syncthreads();

    for (int idx = tid; idx < 2 * DDIM; idx += GT) {
        int bb = idx / DDIM, d = idx - bb * DDIM;
        float o = 0.f;
        #pragma unroll
        for (int l = 0; l < LL; ++l)
            o = fmaf(SAL[bb * LL + l], CT[(bb * LL + l) * 300 + d], o);
        out[(size_t)(blockIdx.x * 2 + bb) * DDIM + d] = o;
    }
}

extern "C" void kernel_launch(void* const* d_in, const int* in_sizes, int n_in,
                              void* d_out, int out_size) {
    const int*   title = (const int*)  d_in[0];
    const float* emb   = (const float*)d_in[1];
    const float* pos   = (const float*)d_in[2];
    const float* Wq    = (const float*)d_in[3];
    const float* bq    = (const float*)d_in[4];
    const float* Wk    = (const float*)d_in[5];
    const float* bk    = (const float*)d_in[6];
    const float* Wv    = (const float*)d_in[7];
    const float* bv    = (const float*)d_in[8];
    const float* Wo    = (const float*)d_in[9];
    const float* bo    = (const float*)d_in[10];
    const float* Va    = (const float*)d_in[11];
    const float* ba    = (const float*)d_in[12];
    const float* qw    = (const float*)d_in[13];
    float* out = (float*)d_out;

    cudaFuncSetAttribute(fused_kernel,
                         cudaFuncAttributeMaxDynamicSharedMemorySize, SMEM_BYTES);

    dim3 pgrid(48, 5);
    prep_kernel<<<pgrid, 256>>>(Wq, Wk, Wv, Wo, Va);

    fused_kernel<<<BB * LL / MT, GT, SMEM_BYTES>>>(title, emb, pos,
                                                   bq, bk, bv, bo, ba, qw, out);
}

// round 11
// speedup vs baseline: 1.5873x; 1.0916x over previous
#include <cuda_runtime.h>
#include <cuda_fp16.h>
#include <math.h>

#define BB 4096
#define LL 32
#define HH 6
#define DDIM 300
#define HDD 50
#define NKC16 19       // k-chunks of 16 (K padded to 304)
#define HS 328         // half-stride of X/K/V rows: conflict-free frag loads
#define MT 64          // rows per CTA = 2 batch rows
#define GT 512         // 16 warps: 2 in M x 8 in N; warp tile 32 x 40

// Fragment-packed fp16 weights (same layout as R10)
#define WB16 (NKC16 * 8 * 5 * 32)
__device__ uint2 g_Wh[5][WB16];

// smem byte offsets
#define X_OFF   0           // half [64][328] : x -> Q -> ctx -> ctx2(fp16)
#define K_OFF   41984       // half [64][328]
#define V_OFF   83968       // half [64][328]
#define CT_OFF  41984       // float [64][300] ctx2 fp32 (overlays K/V after attention)
#define SP_OFF  125952      // float [8][64]
#define SA_OFF  128000      // float [64]
#define SAL_OFF 128256      // float [64]
#define SMEM_BYTES 128512

__device__ __forceinline__ float tanh_fast(float x) {
    float y;
    asm("tanh.approx.f32 %0, %1;" : "=f"(y) : "f"(x));
    return y;
}

__device__ __forceinline__ void mma16(float c[4], const unsigned a[4],
                                      unsigned b0, unsigned b1) {
    asm volatile(
        "mma.sync.aligned.m16n8k16.row.col.f32.f16.f16.f32 "
        "{%0,%1,%2,%3},{%4,%5,%6,%7},{%8,%9},{%0,%1,%2,%3};"
        : "+f"(c[0]), "+f"(c[1]), "+f"(c[2]), "+f"(c[3])
        : "r"(a[0]), "r"(a[1]), "r"(a[2]), "r"(a[3]), "r"(b0), "r"(b1));
}

__device__ __forceinline__ void ldsm4(unsigned a[4], const __half* p) {
    unsigned addr = (unsigned)__cvta_generic_to_shared(p);
    asm volatile("ldmatrix.sync.aligned.m8n8.x4.shared.b16 {%0,%1,%2,%3}, [%4];"
                 : "=r"(a[0]), "=r"(a[1]), "=r"(a[2]), "=r"(a[3]) : "r"(addr));
}

__global__ void prep_kernel(const float* __restrict__ Wq, const float* __restrict__ Wk,
                            const float* __restrict__ Wv, const float* __restrict__ Wo,
                            const float* __restrict__ Va) {
    const float* src;
    int m = blockIdx.y;
    switch (m) {
        case 0: src = Wq; break;
        case 1: src = Wk; break;
        case 2: src = Wv; break;
        case 3: src = Wo; break;
        default: src = Va; break;
    }
    uint2* dst = g_Wh[m];
    for (int idx = blockIdx.x * blockDim.x + threadIdx.x; idx < WB16;
         idx += gridDim.x * blockDim.x) {
        int lane = idx & 31;
        int t1   = idx >> 5;
        int nc   = t1 % 5;
        int t2   = t1 / 5;
        int wn   = t2 & 7;
        int kc   = t2 >> 3;
        int gid = lane >> 2, tig = lane & 3;
        int n = wn * 40 + nc * 8 + gid;
        int k = kc * 16 + 2 * tig;
        float w0 = 0.f, w1 = 0.f, w2 = 0.f, w3 = 0.f;
        if (n < DDIM) {
            if (k < DDIM)     w0 = src[n * DDIM + k];
            if (k + 1 < DDIM) w1 = src[n * DDIM + k + 1];
            if (k + 8 < DDIM) w2 = src[n * DDIM + k + 8];
            if (k + 9 < DDIM) w3 = src[n * DDIM + k + 9];
        }
        uint2 f;
        f.x = (unsigned)__half_as_ushort(__float2half_rn(w0)) |
              ((unsigned)__half_as_ushort(__float2half_rn(w1)) << 16);
        f.y = (unsigned)__half_as_ushort(__float2half_rn(w2)) |
              ((unsigned)__half_as_ushort(__float2half_rn(w3)) << 16);
        dst[idx] = f;
    }
}

// GEMM mainloop: warp tile 32x40. A via ldmatrix.x4 (2/kc), B depth-1 prefetch.
// pa[mf] = per-lane ldmatrix base pointer for row block (wm*32 + mf*16), kc=0.
__device__ __forceinline__ void gemm_main(const __half* __restrict__ pa0,
                                          const __half* __restrict__ pa1,
                                          const uint2* __restrict__ wb0,
                                          float c[2][5][4]) {
    #pragma unroll
    for (int mf = 0; mf < 2; ++mf)
        #pragma unroll
        for (int nc = 0; nc < 5; ++nc)
            #pragma unroll
            for (int i = 0; i < 4; ++i) c[mf][nc][i] = 0.f;

    uint2 bcur[5];
    #pragma unroll
    for (int nc = 0; nc < 5; ++nc) bcur[nc] = wb0[nc * 32];

    #pragma unroll 2
    for (int kc = 0; kc < NKC16; ++kc) {
        uint2 bnxt[5];
        if (kc + 1 < NKC16) {
            const uint2* w2 = wb0 + (size_t)(kc + 1) * (8 * 5 * 32);
            #pragma unroll
            for (int nc = 0; nc < 5; ++nc) bnxt[nc] = w2[nc * 32];
        }
        unsigned a[2][4];
        ldsm4(a[0], pa0 + kc * 16);
        ldsm4(a[1], pa1 + kc * 16);
        #pragma unroll
        for (int nc = 0; nc < 5; ++nc)
            #pragma unroll
            for (int mf = 0; mf < 2; ++mf)
                mma16(c[mf][nc], a[mf], bcur[nc].x, bcur[nc].y);
        #pragma unroll
        for (int nc = 0; nc < 5; ++nc) bcur[nc] = bnxt[nc];
    }
}

__global__ __launch_bounds__(GT, 1)
void fused_kernel(const int* __restrict__ title,
                  const float* __restrict__ emb,
                  const float* __restrict__ pos,
                  const float* __restrict__ bq,
                  const float* __restrict__ bk,
                  const float* __restrict__ bv,
                  const float* __restrict__ bo,
                  const float* __restrict__ ba,
                  const float* __restrict__ qw,
                  float* __restrict__ out) {
    extern __shared__ char smraw[];
    __half* Xsh = (__half*)(smraw + X_OFF);
    __half* SKh = (__half*)(smraw + K_OFF);
    __half* SVh = (__half*)(smraw + V_OFF);
    float*  CT  = (float*)(smraw + CT_OFF);     // stride 300
    float*  SP  = (float*)(smraw + SP_OFF);
    float*  SA  = (float*)(smraw + SA_OFF);
    float*  SAL = (float*)(smraw + SAL_OFF);
    __shared__ int toks[MT];

    const int tid = threadIdx.x;
    const int lane = tid & 31, wid = tid >> 5;
    const int gid = lane >> 2, tig = lane & 3;
    const int wm = wid >> 3, wn = wid & 7;     // 2 x 8 warp grid
    const int r0 = blockIdx.x * MT;

    // ldmatrix per-lane base row/col (kc = 0)
    const int lrow = (lane & 15);
    const int lcol = (lane >> 4) << 3;

    if (tid < MT) toks[tid] = title[r0 + tid];
    __syncthreads();

    // ---- gather x = fp16(emb[tok] + pos); cols 300..327 zero ----
    for (int idx = tid; idx < MT * 82; idx += GT) {
        int r = idx / 82, j = idx - r * 82;
        uint2 o = make_uint2(0u, 0u);
        if (j < 75) {
            float4 e = *(const float4*)&emb[(size_t)toks[r] * DDIM + 4 * j];
            float4 p = *(const float4*)&pos[(r & (LL - 1)) * DDIM + 4 * j];
            __half2 h0 = __floats2half2_rn(e.x + p.x, e.y + p.y);
            __half2 h1 = __floats2half2_rn(e.z + p.z, e.w + p.w);
            o.x = *(unsigned*)&h0;
            o.y = *(unsigned*)&h1;
        }
        *(uint2*)&Xsh[r * HS + 4 * j] = o;
    }
    __syncthreads();

    float c[2][5][4];
    const __half* paX0 = Xsh + (wm * 32 + lrow) * HS + lcol;
    const __half* paX1 = Xsh + (wm * 32 + 16 + lrow) * HS + lcol;

    // ---- K = x @ Wk^T + bk -> SKh ----
    gemm_main(paX0, paX1, g_Wh[1] + (size_t)wn * 5 * 32 + lane, c);
    #pragma unroll
    for (int mf = 0; mf < 2; ++mf)
        #pragma unroll
        for (int nc = 0; nc < 5; ++nc) {
            int n = wn * 40 + nc * 8 + 2 * tig;
            if (n < DDIM) {
                float b0 = bk[n], b1 = bk[n + 1];
                #pragma unroll
                for (int h = 0; h < 2; ++h) {
                    int r = wm * 32 + mf * 16 + gid + h * 8;
                    *(__half2*)&SKh[r * HS + n] =
                        __floats2half2_rn(c[mf][nc][2 * h] + b0, c[mf][nc][2 * h + 1] + b1);
                }
            }
        }

    // ---- V = x @ Wv^T + bv -> SVh ----
    gemm_main(paX0, paX1, g_Wh[2] + (size_t)wn * 5 * 32 + lane, c);
    #pragma unroll
    for (int mf = 0; mf < 2; ++mf)
        #pragma unroll
        for (int nc = 0; nc < 5; ++nc) {
            int n = wn * 40 + nc * 8 + 2 * tig;
            if (n < DDIM) {
                float b0 = bv[n], b1 = bv[n + 1];
                #pragma unroll
                for (int h = 0; h < 2; ++h) {
                    int r = wm * 32 + mf * 16 + gid + h * 8;
                    *(__half2*)&SVh[r * HS + n] =
                        __floats2half2_rn(c[mf][nc][2 * h] + b0, c[mf][nc][2 * h + 1] + b1);
                }
            }
        }

    // ---- Q = (x @ Wq^T + bq)/sqrt(HD) -> Xsh ----
    gemm_main(paX0, paX1, g_Wh[0] + (size_t)wn * 5 * 32 + lane, c);
    const float rs = rsqrtf((float)HDD);
    __syncthreads();                 // all warps done reading x
    #pragma unroll
    for (int mf = 0; mf < 2; ++mf)
        #pragma unroll
        for (int nc = 0; nc < 5; ++nc) {
            int n = wn * 40 + nc * 8 + 2 * tig;
            if (n < DDIM) {
                float b0 = bq[n], b1 = bq[n + 1];
                #pragma unroll
                for (int h = 0; h < 2; ++h) {
                    int r = wm * 32 + mf * 16 + gid + h * 8;
                    *(__half2*)&Xsh[r * HS + n] =
                        __floats2half2_rn((c[mf][nc][2 * h] + b0) * rs,
                                          (c[mf][nc][2 * h + 1] + b1) * rs);
                }
            }
        }
    __syncthreads();

    // ---- attention: 12 (brow,head) tasks over 16 warps (one round) ----
    if (wid < 2 * HH) {
        int br = wid / HH, h = wid - HH * (wid / HH);
        int off = h * HDD;
        const __half* Qb = Xsh + (br * LL) * HS;
        const __half* Kb = SKh + (br * LL) * HS;
        const __half* Vb = SVh + (br * LL) * HS;
        const int i = lane;
        float s[LL];
        #pragma unroll
        for (int j = 0; j < LL; ++j) s[j] = 0.f;
        for (int hd2 = 0; hd2 < HDD / 2; ++hd2) {
            float2 q2 = __half22float2(*(const __half2*)&Qb[i * HS + off + 2 * hd2]);
            #pragma unroll
            for (int j = 0; j < LL; ++j) {
                float2 k2 = __half22float2(*(const __half2*)&Kb[j * HS + off + 2 * hd2]);
                s[j] = fmaf(q2.x, k2.x, fmaf(q2.y, k2.y, s[j]));
            }
        }
        float m = -1e30f;
        #pragma unroll
        for (int j = 0; j < LL; ++j) m = fmaxf(m, s[j]);
        float sum = 0.f;
        #pragma unroll
        for (int j = 0; j < LL; ++j) { s[j] = __expf(s[j] - m); sum += s[j]; }
        float inv = 1.f / sum;
        #pragma unroll
        for (int j = 0; j < LL; ++j) s[j] *= inv;
        for (int hd2 = 0; hd2 < HDD / 2; ++hd2) {
            float cx = 0.f, cy = 0.f;
            #pragma unroll
            for (int j = 0; j < LL; ++j) {
                float2 v2 = __half22float2(*(const __half2*)&Vb[j * HS + off + 2 * hd2]);
                cx = fmaf(s[j], v2.x, cx);
                cy = fmaf(s[j], v2.y, cy);
            }
            *(__half2*)&Xsh[(br * LL + i) * HS + off + 2 * hd2] = __floats2half2_rn(cx, cy);
        }
    }
    __syncthreads();

    // ---- ctx2 = ctx @ Wo^T + bo : fp32 -> CT, fp16 -> Xsh ----
    gemm_main(paX0, paX1, g_Wh[3] + (size_t)wn * 5 * 32 + lane, c);
    __syncthreads();                 // all warps done reading ctx
    #pragma unroll
    for (int mf = 0; mf < 2; ++mf)
        #pragma unroll
        for (int nc = 0; nc < 5; ++nc) {
            int n = wn * 40 + nc * 8 + 2 * tig;
            if (n < DDIM) {
                float b0 = bo[n], b1 = bo[n + 1];
                #pragma unroll
                for (int h = 0; h < 2; ++h) {
                    int r = wm * 32 + mf * 16 + gid + h * 8;
                    float v0 = c[mf][nc][2 * h] + b0;
                    float v1 = c[mf][nc][2 * h + 1] + b1;
                    *(float2*)&CT[r * 300 + n] = make_float2(v0, v1);
                    *(__half2*)&Xsh[r * HS + n] = __floats2half2_rn(v0, v1);
                }
            }
        }
    __syncthreads();

    // ---- scores: a[l] = sum_n tanh(ctx2 @ Va^T + ba)[l][n] * qw[n] ----
    gemm_main(paX0, paX1, g_Wh[4] + (size_t)wn * 5 * 32 + lane, c);
    {
        float p[2][2];
        #pragma unroll
        for (int mf = 0; mf < 2; ++mf) { p[mf][0] = 0.f; p[mf][1] = 0.f; }
        #pragma unroll
        for (int mf = 0; mf < 2; ++mf)
            #pragma unroll
            for (int nc = 0; nc < 5; ++nc)
                #pragma unroll
                for (int i = 0; i < 4; ++i) {
                    int n = wn * 40 + nc * 8 + 2 * tig + (i & 1);
                    if (n < DDIM) {
                        float tv = tanh_fast(c[mf][nc][i] + ba[n]);
                        p[mf][i >> 1] = fmaf(tv, qw[n], p[mf][i >> 1]);
                    }
                }
        #pragma unroll
        for (int mf = 0; mf < 2; ++mf)
            #pragma unroll
            for (int h = 0; h < 2; ++h) {
                float v = p[mf][h];
                v += __shfl_xor_sync(0xffffffffu, v, 1);
                v += __shfl_xor_sync(0xffffffffu, v, 2);
                p[mf][h] = v;
            }
        if (tig == 0) {
            #pragma unroll
            for (int mf = 0; mf < 2; ++mf)
                #pragma unroll
                for (int h = 0; h < 2; ++h) {
                    int r = wm * 32 + mf * 16 + gid + h * 8;
                    SP[wn * MT + r] = p[mf][h];    // wm pairs write disjoint r
                }
        }
    }
    __syncthreads();
    if (tid < MT) {
        float s = 0.f;
        #pragma unroll
        for (int w = 0; w < 8; ++w) s += SP[w * MT + tid];
        SA[tid] = s;
    }
    __syncthreads();

    if (wid < 2) {      // one warp per batch row
        float v = SA[wid * LL + lane];
        float m = v;
        #pragma unroll
        for (int o = 16; o; o >>= 1) m = fmaxf(m, __shfl_xor_sync(0xffffffffu, m, o));
        float e = __expf(v - m);
        float sum = e;
        #pragma unroll
        for (int o = 16; o; o >>= 1) sum += __shfl_xor_sync(0xffffffffu, sum, o);
        SAL[wid * LL + lane] = e / sum;
    }
    __syncthreads();

    for (int idx = tid; idx < 2 * DDIM; idx += GT) {
        int bb = idx / DDIM, d = idx - bb * DDIM;
        float o = 0.f;
        #pragma unroll
        for (int l = 0; l < LL; ++l)
            o = fmaf(SAL[bb * LL + l], CT[(bb * LL + l) * 300 + d], o);
        out[(size_t)(blockIdx.x * 2 + bb) * DDIM + d] = o;
    }
}

extern "C" void kernel_launch(void* const* d_in, const int* in_sizes, int n_in,
                              void* d_out, int out_size) {
    const int*   title = (const int*)  d_in[0];
    const float* emb   = (const float*)d_in[1];
    const float* pos   = (const float*)d_in[2];
    const float* Wq    = (const float*)d_in[3];
    const float* bq    = (const float*)d_in[4];
    const float* Wk    = (const float*)d_in[5];
    const float* bk    = (const float*)d_in[6];
    const float* Wv    = (const float*)d_in[7];
    const float* bv    = (const float*)d_in[8];
    const float* Wo    = (const float*)d_in[9];
    const float* bo    = (const float*)d_in[10];
    const float* Va    = (const float*)d_in[11];
    const float* ba    = (const float*)d_in[12];
    const float* qw    = (const float*)d_in[13];
    float* out = (float*)d_out;

    cudaFuncSetAttribute(fused_kernel,
                         cudaFuncAttributeMaxDynamicSharedMemorySize, SMEM_BYTES);

    dim3 pgrid(48, 5);
    prep_kernel<<<pgrid, 256>>>(Wq, Wk, Wv, Wo, Va);

    fused_kernel<<<BB * LL / MT, GT, SMEM_BYTES>>>(title, emb, pos,
                                                   bq, bk, bv, bo, ba, qw, out);
}